// round 10
// baseline (speedup 1.0000x reference)
#include <cuda_runtime.h>
#include <cuda_fp16.h>
#include <cstdint>

// MeanAggregator: out[b, :] = mean_k features[neigh_idx[b, k], :]
// B=16384, K=15, U=19997, D=256 (idx int32 on device)
//
// Pass 1 (unchanged from R9 win): fp32 -> fp16 shadow table, plain loads
// (table stays L2-resident across graph replays).
// Pass 2: gather via cp.async pipeline. 1 warp = 1 row; each lane stages
// its 16B of each neighbor row into a 6-slot smem ring (cp.async.cg),
// keeping 6 rows in flight per warp independent of register pressure.

#define K_NEIGH 15
#define D_DIM 256
#define U_ROWS 19997
#define WARPS_PER_BLOCK 8
#define CONV_BLOCKS (148 * 8)
#define NTHREADS 256
#define SLOTS 6
#define ROW_BYTES 512            // fp16 row: 256 * 2B

__device__ __half g_feat_h[(size_t)U_ROWS * D_DIM];

// ---- Pass 1: fp32 -> fp16 (8 floats in / 8 halves out per iter) ----
__global__ __launch_bounds__(NTHREADS)
void convert_kernel(const float* __restrict__ f, int n8)
{
    const float4* src = reinterpret_cast<const float4*>(f);
    uint4*        dst = reinterpret_cast<uint4*>(g_feat_h);
    const int stride = gridDim.x * NTHREADS;

    for (int i = blockIdx.x * NTHREADS + threadIdx.x; i < n8; i += stride) {
        float4 a = src[i * 2 + 0];
        float4 b = src[i * 2 + 1];
        uint4 d;
        __half2* h = reinterpret_cast<__half2*>(&d);
        h[0] = __floats2half2_rn(a.x, a.y);
        h[1] = __floats2half2_rn(a.z, a.w);
        h[2] = __floats2half2_rn(b.x, b.y);
        h[3] = __floats2half2_rn(b.z, b.w);
        dst[i] = d;
    }
}

__device__ __forceinline__ void cp_async_16(uint32_t saddr, const void* gaddr)
{
    asm volatile("cp.async.cg.shared.global [%0], [%1], 16;\n"
                 :: "r"(saddr), "l"(gaddr) : "memory");
}
__device__ __forceinline__ void cp_async_commit()
{
    asm volatile("cp.async.commit_group;\n" ::: "memory");
}
__device__ __forceinline__ void cp_async_wait5()
{
    asm volatile("cp.async.wait_group 5;\n" ::: "memory");
}

// ---- Pass 2: gather + mean, cp.async 6-deep row pipeline ----
__global__ __launch_bounds__(NTHREADS)
void gather_kernel(const int* __restrict__ neigh_idx,
                   float* __restrict__ out,
                   int B)
{
    __shared__ int sidx[WARPS_PER_BLOCK][K_NEIGH + 1];
    __shared__ __align__(16) char ring[WARPS_PER_BLOCK][SLOTS][ROW_BYTES];

    const int tid  = threadIdx.x;
    const int warp = tid >> 5;
    const int lane = tid & 31;
    const int row0 = blockIdx.x * WARPS_PER_BLOCK;

    if (tid < WARPS_PER_BLOCK * K_NEIGH) {
        const int r = tid / K_NEIGH, c = tid % K_NEIGH;
        if (row0 + r < B) sidx[r][c] = neigh_idx[(row0 + r) * K_NEIGH + c];
    }
    __syncthreads();

    const int row = row0 + warp;
    if (row >= B) return;

    const char* __restrict__ fbytes = reinterpret_cast<const char*>(g_feat_h);
    const uint32_t slane = (uint32_t)__cvta_generic_to_shared(&ring[warp][0][lane * 16]);

    // Prologue: stage rows 0..5, one commit-group per row.
    #pragma unroll
    for (int p = 0; p < SLOTS; ++p) {
        const char* g = fbytes + (size_t)sidx[warp][p] * ROW_BYTES + lane * 16;
        cp_async_16(slane + p * ROW_BYTES, g);
        cp_async_commit();
    }

    float acc[8] = {0.f, 0.f, 0.f, 0.f, 0.f, 0.f, 0.f, 0.f};

    #pragma unroll
    for (int k = 0; k < K_NEIGH; ++k) {
        cp_async_wait5();                 // oldest group (row k) has landed

        const uint4 v = *reinterpret_cast<const uint4*>(&ring[warp][k % SLOTS][lane * 16]);
        const __half2* h = reinterpret_cast<const __half2*>(&v);
        #pragma unroll
        for (int j = 0; j < 4; ++j) {
            float2 p = __half22float2(h[j]);
            acc[j * 2]     += p.x;
            acc[j * 2 + 1] += p.y;
        }

        const int nxt = k + SLOTS;
        if (nxt < K_NEIGH) {
            const char* g = fbytes + (size_t)sidx[warp][nxt] * ROW_BYTES + lane * 16;
            cp_async_16(slane + (nxt % SLOTS) * ROW_BYTES, g);
        }
        cp_async_commit();                // commit (possibly empty) keeps counts uniform
    }

    const float inv = 1.0f / (float)K_NEIGH;
    float4 o0 = make_float4(acc[0]*inv, acc[1]*inv, acc[2]*inv, acc[3]*inv);
    float4 o1 = make_float4(acc[4]*inv, acc[5]*inv, acc[6]*inv, acc[7]*inv);

    float4* __restrict__ op = reinterpret_cast<float4*>(out + (size_t)row * D_DIM + lane * 8);
    op[0] = o0;
    op[1] = o1;
}

extern "C" void kernel_launch(void* const* d_in, const int* in_sizes, int n_in,
                              void* d_out, int out_size)
{
    int idx_slot = 0, feat_slot = 1;
    if (n_in >= 2 && in_sizes[0] > in_sizes[1]) { idx_slot = 1; feat_slot = 0; }

    const int*   neigh_idx = (const int*)d_in[idx_slot];     // [B, K] int32
    const float* features  = (const float*)d_in[feat_slot];  // [U, D] fp32
    float*       out       = (float*)d_out;                  // [B, D] fp32

    const int B  = in_sizes[idx_slot] / K_NEIGH;
    const int n8 = in_sizes[feat_slot] / 8;                  // 639,904

    convert_kernel<<<CONV_BLOCKS, NTHREADS>>>(features, n8);

    dim3 block(NTHREADS);
    dim3 grid((B + WARPS_PER_BLOCK - 1) / WARPS_PER_BLOCK);
    gather_kernel<<<grid, block>>>(neigh_idx, out, B);
}

// round 11
// speedup vs baseline: 1.1457x; 1.1457x over previous
#include <cuda_runtime.h>
#include <cuda_fp16.h>
#include <cstdint>

// MeanAggregator: out[b, :] = mean_k features[neigh_idx[b, k], :]
// B=16384, K=15, U=19997, D=256 (idx int32 on device)
//
// Two kernels (R9 structure, measured best):
//  1) convert: fp32 table -> fp16 shadow, one 32B->16B chunk per thread,
//     plain loads so the fp32 table stays L2-resident across graph replays.
//  2) gather: grid 2048 x 256, 1 warp = 1 row, 15 back-to-back LDG.128
//     per lane from the fp16 table, fp32 accumulate, fp32 out.
//     Indices pre-scaled to uint4-row offsets in smem.

#define K_NEIGH 15
#define D_DIM 256
#define U_ROWS 19997
#define WARPS_PER_BLOCK 8
#define NTHREADS 256

__device__ __half g_feat_h[(size_t)U_ROWS * D_DIM];

// ---- Pass 1: fp32 -> fp16 (8 floats in / 8 halves out per thread) ----
__global__ __launch_bounds__(NTHREADS)
void convert_kernel(const float* __restrict__ f, int n8)
{
    const int i = blockIdx.x * NTHREADS + threadIdx.x;
    if (i >= n8) return;

    const float4* src = reinterpret_cast<const float4*>(f);
    float4 a = src[i * 2 + 0];
    float4 b = src[i * 2 + 1];
    uint4 d;
    __half2* h = reinterpret_cast<__half2*>(&d);
    h[0] = __floats2half2_rn(a.x, a.y);
    h[1] = __floats2half2_rn(a.z, a.w);
    h[2] = __floats2half2_rn(b.x, b.y);
    h[3] = __floats2half2_rn(b.z, b.w);
    reinterpret_cast<uint4*>(g_feat_h)[i] = d;
}

// ---- Pass 2: gather + mean. One warp per output row. ----
__global__ __launch_bounds__(NTHREADS)
void gather_kernel(const int* __restrict__ neigh_idx,
                   float* __restrict__ out,
                   int B)
{
    __shared__ int soff[WARPS_PER_BLOCK][K_NEIGH + 1];   // uint4-row offsets

    const int tid  = threadIdx.x;
    const int warp = tid >> 5;
    const int lane = tid & 31;
    const int row0 = blockIdx.x * WARPS_PER_BLOCK;

    if (tid < WARPS_PER_BLOCK * K_NEIGH) {
        const int r = tid / K_NEIGH, c = tid % K_NEIGH;
        if (row0 + r < B)
            soff[r][c] = neigh_idx[(row0 + r) * K_NEIGH + c] * (D_DIM / 8);
    }
    __syncthreads();

    const int row = row0 + warp;
    if (row >= B) return;

    const uint4* __restrict__ f = reinterpret_cast<const uint4*>(g_feat_h);

    float acc[8] = {0.f, 0.f, 0.f, 0.f, 0.f, 0.f, 0.f, 0.f};

    #pragma unroll
    for (int k = 0; k < K_NEIGH; ++k) {
        const uint4 v = f[soff[warp][k] + lane];         // 32 uint4 per row
        const __half2* h = reinterpret_cast<const __half2*>(&v);
        #pragma unroll
        for (int j = 0; j < 4; ++j) {
            float2 p = __half22float2(h[j]);
            acc[j * 2]     += p.x;
            acc[j * 2 + 1] += p.y;
        }
    }

    const float inv = 1.0f / (float)K_NEIGH;
    float4 o0 = make_float4(acc[0]*inv, acc[1]*inv, acc[2]*inv, acc[3]*inv);
    float4 o1 = make_float4(acc[4]*inv, acc[5]*inv, acc[6]*inv, acc[7]*inv);

    float4* __restrict__ op = reinterpret_cast<float4*>(out + (size_t)row * D_DIM + lane * 8);
    op[0] = o0;
    op[1] = o1;
}

extern "C" void kernel_launch(void* const* d_in, const int* in_sizes, int n_in,
                              void* d_out, int out_size)
{
    int idx_slot = 0, feat_slot = 1;
    if (n_in >= 2 && in_sizes[0] > in_sizes[1]) { idx_slot = 1; feat_slot = 0; }

    const int*   neigh_idx = (const int*)d_in[idx_slot];     // [B, K] int32
    const float* features  = (const float*)d_in[feat_slot];  // [U, D] fp32
    float*       out       = (float*)d_out;                  // [B, D] fp32

    const int B  = in_sizes[idx_slot] / K_NEIGH;
    const int n8 = in_sizes[feat_slot] / 8;                  // 639,904

    convert_kernel<<<(n8 + NTHREADS - 1) / NTHREADS, NTHREADS>>>(features, n8);

    dim3 block(NTHREADS);
    dim3 grid((B + WARPS_PER_BLOCK - 1) / WARPS_PER_BLOCK);
    gather_kernel<<<grid, block>>>(neigh_idx, out, B);
}

// round 12
// speedup vs baseline: 1.1958x; 1.0437x over previous
#include <cuda_runtime.h>
#include <cuda_fp16.h>
#include <cstdint>

// MeanAggregator: out[b, :] = mean_k features[neigh_idx[b, k], :]
// B=16384, K=15, U=19997, D=256 (idx int32 on device)
//
// Combination of the two measured-best components:
//  1) convert (R9): fp32 -> fp16 shadow, grid-stride 1184x256, plain loads
//     (fp32 table stays L2-resident across graph replays)  [~2.7us]
//  2) gather (R11): grid 2048x256, 1 warp = 1 row, indices pre-scaled to
//     uint4-row offsets in smem, 15 back-to-back LDG.128 per lane,
//     fp32 accumulate, fp32 out  [13.6us]

#define K_NEIGH 15
#define D_DIM 256
#define U_ROWS 19997
#define WARPS_PER_BLOCK 8
#define CONV_BLOCKS (148 * 8)
#define NTHREADS 256

__device__ __half g_feat_h[(size_t)U_ROWS * D_DIM];

// ---- Pass 1: fp32 -> fp16 (8 floats in / 8 halves out per iter) ----
__global__ __launch_bounds__(NTHREADS)
void convert_kernel(const float* __restrict__ f, int n8)
{
    const float4* src = reinterpret_cast<const float4*>(f);
    uint4*        dst = reinterpret_cast<uint4*>(g_feat_h);
    const int stride = gridDim.x * NTHREADS;

    for (int i = blockIdx.x * NTHREADS + threadIdx.x; i < n8; i += stride) {
        float4 a = src[i * 2 + 0];
        float4 b = src[i * 2 + 1];
        uint4 d;
        __half2* h = reinterpret_cast<__half2*>(&d);
        h[0] = __floats2half2_rn(a.x, a.y);
        h[1] = __floats2half2_rn(a.z, a.w);
        h[2] = __floats2half2_rn(b.x, b.y);
        h[3] = __floats2half2_rn(b.z, b.w);
        dst[i] = d;
    }
}

// ---- Pass 2: gather + mean. One warp per output row. ----
__global__ __launch_bounds__(NTHREADS)
void gather_kernel(const int* __restrict__ neigh_idx,
                   float* __restrict__ out,
                   int B)
{
    __shared__ int soff[WARPS_PER_BLOCK][K_NEIGH + 1];   // uint4-row offsets

    const int tid  = threadIdx.x;
    const int warp = tid >> 5;
    const int lane = tid & 31;
    const int row0 = blockIdx.x * WARPS_PER_BLOCK;

    if (tid < WARPS_PER_BLOCK * K_NEIGH) {
        const int r = tid / K_NEIGH, c = tid % K_NEIGH;
        if (row0 + r < B)
            soff[r][c] = neigh_idx[(row0 + r) * K_NEIGH + c] * (D_DIM / 8);
    }
    __syncthreads();

    const int row = row0 + warp;
    if (row >= B) return;

    const uint4* __restrict__ f = reinterpret_cast<const uint4*>(g_feat_h);

    float acc[8] = {0.f, 0.f, 0.f, 0.f, 0.f, 0.f, 0.f, 0.f};

    #pragma unroll
    for (int k = 0; k < K_NEIGH; ++k) {
        const uint4 v = f[soff[warp][k] + lane];         // 32 uint4 per row
        const __half2* h = reinterpret_cast<const __half2*>(&v);
        #pragma unroll
        for (int j = 0; j < 4; ++j) {
            float2 p = __half22float2(h[j]);
            acc[j * 2]     += p.x;
            acc[j * 2 + 1] += p.y;
        }
    }

    const float inv = 1.0f / (float)K_NEIGH;
    float4 o0 = make_float4(acc[0]*inv, acc[1]*inv, acc[2]*inv, acc[3]*inv);
    float4 o1 = make_float4(acc[4]*inv, acc[5]*inv, acc[6]*inv, acc[7]*inv);

    float4* __restrict__ op = reinterpret_cast<float4*>(out + (size_t)row * D_DIM + lane * 8);
    op[0] = o0;
    op[1] = o1;
}

extern "C" void kernel_launch(void* const* d_in, const int* in_sizes, int n_in,
                              void* d_out, int out_size)
{
    int idx_slot = 0, feat_slot = 1;
    if (n_in >= 2 && in_sizes[0] > in_sizes[1]) { idx_slot = 1; feat_slot = 0; }

    const int*   neigh_idx = (const int*)d_in[idx_slot];     // [B, K] int32
    const float* features  = (const float*)d_in[feat_slot];  // [U, D] fp32
    float*       out       = (float*)d_out;                  // [B, D] fp32

    const int B  = in_sizes[idx_slot] / K_NEIGH;
    const int n8 = in_sizes[feat_slot] / 8;                  // 639,904

    convert_kernel<<<CONV_BLOCKS, NTHREADS>>>(features, n8);

    dim3 block(NTHREADS);
    dim3 grid((B + WARPS_PER_BLOCK - 1) / WARPS_PER_BLOCK);
    gather_kernel<<<grid, block>>>(neigh_idx, out, B);
}